// round 1
// baseline (speedup 1.0000x reference)
#include <cuda_runtime.h>
#include <math.h>

#define BSZ 16
#define SEQ 512
#define DM 512
#define DI 1024
#define DS 32
#define DTR 32
#define NROWS (BSZ*SEQ)   /* 8192 */

/* ---------------- scratch (static device memory; no allocations) ---------- */
/* layout (floats):
   u     : NROWS*DM      = 4,194,304
   xz    : NROWS*2*DI    = 16,777,216
   xc    : NROWS*DI      = 8,388,608
   xdbc  : NROWS*96      = 786,432
   dt    : NROWS*DI      = 8,388,608
   y     : NROWS*DI      = 8,388,608
   lnin  : NROWS*DM      = 4,194,304
   mout  : 2*NROWS*DM    = 8,388,608
   total = 59,506,688 floats (~238 MB)                                        */
#define OFF_U    ((size_t)0)
#define OFF_XZ   (OFF_U    + (size_t)NROWS*DM)
#define OFF_XC   (OFF_XZ   + (size_t)NROWS*2*DI)
#define OFF_XDBC (OFF_XC   + (size_t)NROWS*DI)
#define OFF_DT   (OFF_XDBC + (size_t)NROWS*96)
#define OFF_Y    (OFF_DT   + (size_t)NROWS*DI)
#define OFF_LNIN (OFF_Y    + (size_t)NROWS*DI)
#define OFF_MOUT (OFF_LNIN + (size_t)NROWS*DM)
#define SCR_TOTAL (OFF_MOUT + (size_t)2*NROWS*DM)

__device__ __align__(16) float g_scr[SCR_TOTAL];

/* ---------------- embedding: conv token embed + temporal + positional ----- */
__global__ __launch_bounds__(512)
void emb_kernel(const float* __restrict__ x_enc, const float* __restrict__ x_mark,
                const float* __restrict__ cw, const float* __restrict__ tw)
{
    __shared__ float xs[34][32];
    __shared__ float xm[32][4];
    const int b  = blockIdx.x >> 4;
    const int l0 = (blockIdx.x & 15) * 32;
    const int d  = threadIdx.x;

    for (int i = d; i < 34 * 32; i += 512) {
        int r = i >> 5, c = i & 31;
        int g = l0 - 2 + r;
        g = max(0, min(SEQ - 1, g));
        xs[r][c] = x_enc[((size_t)b * SEQ + g) * 32 + c];
    }
    for (int i = d; i < 32 * 4; i += 512) {
        int r = i >> 2, m = i & 3;
        xm[r][m] = x_mark[((size_t)b * SEQ + l0 + r) * 4 + m];
    }
    __syncthreads();

    float w[96];
#pragma unroll
    for (int i = 0; i < 96; i++) w[i] = cw[d * 96 + i];
    const float t0w = tw[d * 4 + 0], t1w = tw[d * 4 + 1];
    const float t2w = tw[d * 4 + 2], t3w = tw[d * 4 + 3];
    const float divv = __expf(-(float)(d & ~1) * (9.2103403719761836f / 512.f));

    for (int ll = 0; ll < 32; ll++) {
        int l = l0 + ll;
        float ang = (float)l * divv;
        float acc = (d & 1) ? cosf(ang) : sinf(ang);
        acc += t0w * xm[ll][0] + t1w * xm[ll][1] + t2w * xm[ll][2] + t3w * xm[ll][3];
#pragma unroll
        for (int ci = 0; ci < 32; ci++) {
            acc += w[ci * 3 + 0] * xs[ll + 0][ci];
            acc += w[ci * 3 + 1] * xs[ll + 1][ci];
            acc += w[ci * 3 + 2] * xs[ll + 2][ci];
        }
        g_scr[OFF_U + ((size_t)b * SEQ + l) * DM + d] = acc;
    }
}

/* ---------------- generic fp32 GEMM: C[M,N] = A[M,K] * W[N,K]^T ----------- */
/* epi==1: softplus(v + bias[n])                                             */
#define BM 128
#define BN 128
#define BKK 8

__global__ __launch_bounds__(256, 2)
void gemm_kernel(const float* __restrict__ A, const float* __restrict__ W,
                 float* __restrict__ C, const float* __restrict__ bias,
                 int M, int N, int K, int lda, int ldw, int ldc, int epi)
{
    __shared__ float As[BKK][BM];
    __shared__ float Ws[BKK][BN];
    const int tid = threadIdx.x;
    const int m0 = blockIdx.y * BM;
    const int n0 = blockIdx.x * BN;
    const int lr = tid >> 1;
    const int lc = (tid & 1) << 2;
    const int tx = tid & 15;
    const int ty = tid >> 4;

    float acc[8][8];
#pragma unroll
    for (int i = 0; i < 8; i++)
#pragma unroll
        for (int j = 0; j < 8; j++) acc[i][j] = 0.f;

    const float* Ap = A + (size_t)(m0 + lr) * lda + lc;
    const float* Wp = W + (size_t)(n0 + lr) * ldw + lc;
    const bool a_ok = (m0 + lr) < M;
    const bool w_ok = (n0 + lr) < N;

    float4 a_reg = a_ok ? *(const float4*)Ap : make_float4(0, 0, 0, 0);
    float4 w_reg = w_ok ? *(const float4*)Wp : make_float4(0, 0, 0, 0);

    for (int k0 = 0; k0 < K; k0 += BKK) {
        As[lc + 0][lr] = a_reg.x; As[lc + 1][lr] = a_reg.y;
        As[lc + 2][lr] = a_reg.z; As[lc + 3][lr] = a_reg.w;
        Ws[lc + 0][lr] = w_reg.x; Ws[lc + 1][lr] = w_reg.y;
        Ws[lc + 2][lr] = w_reg.z; Ws[lc + 3][lr] = w_reg.w;
        __syncthreads();
        if (k0 + BKK < K) {
            a_reg = a_ok ? *(const float4*)(Ap + k0 + BKK) : make_float4(0, 0, 0, 0);
            w_reg = w_ok ? *(const float4*)(Wp + k0 + BKK) : make_float4(0, 0, 0, 0);
        }
#pragma unroll
        for (int kk = 0; kk < BKK; kk++) {
            float4 a0 = *(const float4*)&As[kk][ty * 8];
            float4 a1 = *(const float4*)&As[kk][ty * 8 + 4];
            float4 b0 = *(const float4*)&Ws[kk][tx * 8];
            float4 b1 = *(const float4*)&Ws[kk][tx * 8 + 4];
            float av[8] = {a0.x, a0.y, a0.z, a0.w, a1.x, a1.y, a1.z, a1.w};
            float bv[8] = {b0.x, b0.y, b0.z, b0.w, b1.x, b1.y, b1.z, b1.w};
#pragma unroll
            for (int i = 0; i < 8; i++)
#pragma unroll
                for (int j = 0; j < 8; j++)
                    acc[i][j] = fmaf(av[i], bv[j], acc[i][j]);
        }
        __syncthreads();
    }

#pragma unroll
    for (int i = 0; i < 8; i++) {
        int m = m0 + ty * 8 + i;
        if (m >= M) continue;
#pragma unroll
        for (int j = 0; j < 8; j++) {
            int n = n0 + tx * 8 + j;
            if (n >= N) continue;
            float v = acc[i][j];
            if (epi == 1) {
                v += bias[n];
                v = (v > 20.f) ? v : log1pf(__expf(v));
            }
            C[(size_t)m * ldc + n] = v;
        }
    }
}

/* ---------------- depthwise causal conv (D_CONV=4) + bias + silu ---------- */
__global__ __launch_bounds__(256)
void conv_silu_kernel(const float* __restrict__ cw, const float* __restrict__ cb)
{
    int idx = blockIdx.x * 256 + threadIdx.x;
    if (idx >= NROWS * DI) return;
    const int d  = idx & (DI - 1);
    const int bl = idx >> 10;
    const int l  = bl & (SEQ - 1);
    const float* xz = g_scr + OFF_XZ;
    float acc = cb[d];
#pragma unroll
    for (int k = 0; k < 4; k++) {
        int ls = l - 3 + k;
        if (ls >= 0) acc += cw[d * 4 + k] * xz[(size_t)(bl - l + ls) * 2048 + d];
    }
    float sig = 1.f / (1.f + __expf(-acc));
    g_scr[OFF_XC + (size_t)idx] = acc * sig;
}

/* ---------------- selective scan: warp per (b,d), lane = state ------------ */
#define TCH 64
__global__ __launch_bounds__(256)
void scan_kernel(const float* __restrict__ A_log, const float* __restrict__ Dvec)
{
    __shared__ float Bs[TCH][DS];
    __shared__ float Cs[TCH][DS];
    const int warp = threadIdx.x >> 5;
    const int lane = threadIdx.x & 31;
    const int gw = blockIdx.x * 8 + warp;    /* 0..16383 */
    const int b = gw >> 10;
    const int d = gw & (DI - 1);

    const float a  = -__expf(A_log[d * DS + lane]);
    const float Dd = Dvec[d];

    const float* dt_p = g_scr + OFF_DT   + (size_t)(b * SEQ) * DI + d;
    const float* x_p  = g_scr + OFF_XC   + (size_t)(b * SEQ) * DI + d;
    const float* z_p  = g_scr + OFF_XZ   + (size_t)(b * SEQ) * 2048 + DI + d;
    const float* B_p  = g_scr + OFF_XDBC + (size_t)(b * SEQ) * 96 + DTR;
    const float* C_p  = B_p + DS;
    float*       y_p  = g_scr + OFF_Y    + (size_t)(b * SEQ) * DI + d;

    float h = 0.f;
    for (int t0 = 0; t0 < SEQ; t0 += TCH) {
        __syncthreads();
        for (int i = threadIdx.x; i < TCH * DS; i += 256) {
            int tt = i >> 5, s = i & 31;
            Bs[tt][s] = B_p[(size_t)(t0 + tt) * 96 + s];
            Cs[tt][s] = C_p[(size_t)(t0 + tt) * 96 + s];
        }
        __syncthreads();
        for (int tt = 0; tt < TCH; tt++) {
            int t = t0 + tt;
            float dtv = __ldg(dt_p + (size_t)t * DI);
            float xv  = __ldg(x_p  + (size_t)t * DI);
            float zv  = __ldg(z_p  + (size_t)t * 2048);
            float dA = __expf(dtv * a);
            h = fmaf(dA, h, dtv * xv * Bs[tt][lane]);
            float p = h * Cs[tt][lane];
#pragma unroll
            for (int off = 16; off; off >>= 1)
                p += __shfl_xor_sync(0xffffffffu, p, off);
            if (lane == 0) {
                float sig = 1.f / (1.f + __expf(-zv));
                y_p[(size_t)t * DI] = (p + xv * Dd) * zv * sig;
            }
        }
    }
}

/* ---------------- layernorm over D_MODEL=512, writes mout + next-iter u --- */
__global__ __launch_bounds__(512)
void ln_kernel(const float* __restrict__ in, const float* __restrict__ w,
               const float* __restrict__ bb, int iter)
{
    const int row = blockIdx.x;   /* 0..8191 = b*512+t */
    const int d = threadIdx.x;
    float v = in[(size_t)row * DM + d];
    float s = v, s2 = v * v;
#pragma unroll
    for (int off = 16; off; off >>= 1) {
        s  += __shfl_xor_sync(0xffffffffu, s,  off);
        s2 += __shfl_xor_sync(0xffffffffu, s2, off);
    }
    __shared__ float sh1[16], sh2[16];
    __shared__ float mu_s, rs_s;
    const int wid = d >> 5, lane = d & 31;
    if (lane == 0) { sh1[wid] = s; sh2[wid] = s2; }
    __syncthreads();
    if (d < 32) {
        float aa = (d < 16) ? sh1[d] : 0.f;
        float cc = (d < 16) ? sh2[d] : 0.f;
#pragma unroll
        for (int off = 8; off; off >>= 1) {
            aa += __shfl_xor_sync(0xffffffffu, aa, off);
            cc += __shfl_xor_sync(0xffffffffu, cc, off);
        }
        if (d == 0) {
            float mu = aa / (float)DM;
            float var = cc / (float)DM - mu * mu;
            mu_s = mu;
            rs_s = rsqrtf(var + 1e-5f);
        }
    }
    __syncthreads();
    float o = (v - mu_s) * rs_s * w[d] + bb[d];
    const int bidx = row >> 9, t = row & 511;
    g_scr[OFF_MOUT + (((size_t)bidx * 1024) + (size_t)iter * SEQ + t) * DM + d] = o;
    g_scr[OFF_U + (size_t)row * DM + d] = o;
}

/* ---------------- launch --------------------------------------------------- */
extern "C" void kernel_launch(void* const* d_in, const int* in_sizes, int n_in,
                              void* d_out, int out_size)
{
    const float* x_enc      = (const float*)d_in[0];
    const float* x_mark_enc = (const float*)d_in[1];
    const float* conv_emb_w = (const float*)d_in[4];
    const float* temp_w     = (const float*)d_in[5];
    const float* in_proj_w  = (const float*)d_in[6];
    const float* conv1d_w   = (const float*)d_in[7];
    const float* conv1d_b   = (const float*)d_in[8];
    const float* x_proj_w   = (const float*)d_in[9];
    const float* dt_proj_w  = (const float*)d_in[10];
    const float* dt_proj_b  = (const float*)d_in[11];
    const float* A_log      = (const float*)d_in[12];
    const float* Dvec       = (const float*)d_in[13];
    const float* out_proj_w = (const float*)d_in[14];
    const float* ln_w       = (const float*)d_in[15];
    const float* ln_b       = (const float*)d_in[16];
    const float* head_w     = (const float*)d_in[17];
    float* out = (float*)d_out;

    float* scr = nullptr;
    cudaGetSymbolAddress((void**)&scr, g_scr);
    float* u    = scr + OFF_U;
    float* xz   = scr + OFF_XZ;
    float* xc   = scr + OFF_XC;
    float* xdbc = scr + OFF_XDBC;
    float* dt   = scr + OFF_DT;
    float* y    = scr + OFF_Y;
    float* lnin = scr + OFF_LNIN;
    float* mout = scr + OFF_MOUT;

    emb_kernel<<<256, 512>>>(x_enc, x_mark_enc, conv_emb_w, temp_w);

    for (int iter = 0; iter < 2; iter++) {
        /* xz = u @ in_proj^T : (8192,2048) */
        gemm_kernel<<<dim3(2048 / BN, 8192 / BM), 256>>>(
            u, in_proj_w, xz, nullptr, 8192, 2048, 512, 512, 512, 2048, 0);
        /* depthwise conv + silu -> xc */
        conv_silu_kernel<<<(NROWS * DI) / 256, 256>>>(conv1d_w, conv1d_b);
        /* xdbc = xc @ x_proj^T : (8192,96) */
        gemm_kernel<<<dim3(1, 8192 / BM), 256>>>(
            xc, x_proj_w, xdbc, nullptr, 8192, 96, 1024, 1024, 1024, 96, 0);
        /* dt = softplus(xdbc[:,:32] @ dt_proj^T + b) : (8192,1024) */
        gemm_kernel<<<dim3(1024 / BN, 8192 / BM), 256>>>(
            xdbc, dt_proj_w, dt, dt_proj_b, 8192, 1024, 32, 96, 32, 1024, 1);
        /* selective scan + gating -> y */
        scan_kernel<<<2048, 256>>>(A_log, Dvec);
        /* lnin = y @ out_proj^T : (8192,512) */
        gemm_kernel<<<dim3(512 / BN, 8192 / BM), 256>>>(
            y, out_proj_w, lnin, nullptr, 8192, 512, 1024, 1024, 1024, 512, 0);
        /* layernorm -> mout slice + next u */
        ln_kernel<<<8192, 512>>>(lnin, ln_w, ln_b, iter);
    }

    /* out = mout @ head^T : (16384,32) */
    gemm_kernel<<<dim3(1, 16384 / BM), 256>>>(
        mout, head_w, out, nullptr, 16384, 32, 512, 512, 512, 32, 0);
}

// round 4
// speedup vs baseline: 1.1469x; 1.1469x over previous
#include <cuda_runtime.h>
#include <math.h>
#include <cstdint>

#define BSZ 16
#define SEQ 512
#define DM 512
#define DI 1024
#define DS 32
#define DTR 32
#define NROWS (BSZ*SEQ)   /* 8192 */

/* ---------------- scratch (static device memory; no allocations) ---------- */
#define OFF_U    ((size_t)0)
#define OFF_XZ   (OFF_U    + (size_t)NROWS*DM)
#define OFF_XC   (OFF_XZ   + (size_t)NROWS*2*DI)
#define OFF_XDBC (OFF_XC   + (size_t)NROWS*DI)
#define OFF_DT   (OFF_XDBC + (size_t)NROWS*96)
#define OFF_Y    (OFF_DT   + (size_t)NROWS*DI)
#define OFF_LNIN (OFF_Y    + (size_t)NROWS*DI)
#define OFF_MOUT (OFF_LNIN + (size_t)NROWS*DM)
#define SCR_TOTAL (OFF_MOUT + (size_t)2*NROWS*DM)

__device__ __align__(16) float g_scr[SCR_TOTAL];

/* ---------------- embedding: conv token embed + temporal + positional ----- */
__global__ __launch_bounds__(512)
void emb_kernel(const float* __restrict__ x_enc, const float* __restrict__ x_mark,
                const float* __restrict__ cw, const float* __restrict__ tw)
{
    __shared__ float xs[34][32];
    __shared__ float xm[32][4];
    const int b  = blockIdx.x >> 4;
    const int l0 = (blockIdx.x & 15) * 32;
    const int d  = threadIdx.x;

    for (int i = d; i < 34 * 32; i += 512) {
        int r = i >> 5, c = i & 31;
        int g = l0 - 2 + r;
        g = max(0, min(SEQ - 1, g));
        xs[r][c] = x_enc[((size_t)b * SEQ + g) * 32 + c];
    }
    for (int i = d; i < 32 * 4; i += 512) {
        int r = i >> 2, m = i & 3;
        xm[r][m] = x_mark[((size_t)b * SEQ + l0 + r) * 4 + m];
    }
    __syncthreads();

    float w[96];
#pragma unroll
    for (int i = 0; i < 96; i++) w[i] = cw[d * 96 + i];
    const float t0w = tw[d * 4 + 0], t1w = tw[d * 4 + 1];
    const float t2w = tw[d * 4 + 2], t3w = tw[d * 4 + 3];
    const float divv = __expf(-(float)(d & ~1) * (9.2103403719761836f / 512.f));

    for (int ll = 0; ll < 32; ll++) {
        int l = l0 + ll;
        float ang = (float)l * divv;
        float acc = (d & 1) ? cosf(ang) : sinf(ang);
        acc += t0w * xm[ll][0] + t1w * xm[ll][1] + t2w * xm[ll][2] + t3w * xm[ll][3];
#pragma unroll
        for (int ci = 0; ci < 32; ci++) {
            acc += w[ci * 3 + 0] * xs[ll + 0][ci];
            acc += w[ci * 3 + 1] * xs[ll + 1][ci];
            acc += w[ci * 3 + 2] * xs[ll + 2][ci];
        }
        g_scr[OFF_U + ((size_t)b * SEQ + l) * DM + d] = acc;
    }
}

/* =========== 3xTF32 tensor-core GEMM: C[M,N] = A[M,K] * W[N,K]^T ========== */
/* mma.sync.m16n8k8.tf32 with hi/lo split (near-fp32 accuracy).
   128x128x32 block tile, 16 warps (4x4), warp tile 32x32.
   cp.async 2-stage pipeline. epi==1: softplus(v + bias[n]).                 */
#define GBM 128
#define GBN 128
#define GSTR 36                    /* padded row stride in floats */
#define STAGE_F (2 * GBM * GSTR)   /* floats per stage (A+B) */
#define GT_SMEM_BYTES (2 * STAGE_F * 4)

__device__ __forceinline__ void cp_async16(uint32_t dst, const void* src, int sz) {
    asm volatile("cp.async.cg.shared.global [%0], [%1], 16, %2;"
                 :: "r"(dst), "l"(src), "r"(sz));
}
#define CP_COMMIT() asm volatile("cp.async.commit_group;" ::: "memory")
#define CP_WAIT1()  asm volatile("cp.async.wait_group 1;" ::: "memory")

__device__ __forceinline__ uint32_t f2tf(float x) {
    uint32_t r;
    asm("cvt.rna.tf32.f32 %0, %1;" : "=r"(r) : "f"(x));
    return r;
}
__device__ __forceinline__ void split_tf(float v, uint32_t& hi, uint32_t& lo) {
    hi = f2tf(v);
    lo = f2tf(v - __uint_as_float(hi));
}

__device__ __forceinline__ void mma_tf32(float* c, const uint32_t* a, const uint32_t* b) {
    asm volatile(
        "mma.sync.aligned.m16n8k8.row.col.f32.tf32.tf32.f32 "
        "{%0,%1,%2,%3}, {%4,%5,%6,%7}, {%8,%9}, {%0,%1,%2,%3};"
        : "+f"(c[0]), "+f"(c[1]), "+f"(c[2]), "+f"(c[3])
        : "r"(a[0]), "r"(a[1]), "r"(a[2]), "r"(a[3]), "r"(b[0]), "r"(b[1]));
}

__global__ __launch_bounds__(512, 1)
void gemm_mma(const float* __restrict__ A, const float* __restrict__ W,
              float* __restrict__ C, const float* __restrict__ bias,
              int M, int N, int K, int lda, int ldw, int ldc, int epi)
{
    extern __shared__ __align__(16) float smem[];
    uint32_t smem_u32;
    asm("{ .reg .u64 t; cvta.to.shared.u64 t, %1; cvt.u32.u64 %0, t; }"
        : "=r"(smem_u32) : "l"(smem));

    const int tid = threadIdx.x;
    const int wid = tid >> 5;
    const int lane = tid & 31;
    const int m0 = blockIdx.y * GBM;
    const int n0 = blockIdx.x * GBN;
    const int warp_m = (wid >> 2) * 32;   /* 0,32,64,96 */
    const int warp_n = (wid & 3) * 32;    /* 0,32,64,96 */
    const int gid = lane >> 2;            /* groupID */
    const int tig = lane & 3;             /* thread in group */

    float acc[2][4][4];
#pragma unroll
    for (int i = 0; i < 2; i++)
#pragma unroll
        for (int j = 0; j < 4; j++)
#pragma unroll
            for (int k = 0; k < 4; k++) acc[i][j][k] = 0.f;

    const int nch = K >> 5;

    /* stage loader: 2048 16B copies, 4 per thread */
#define LOAD_STAGE(c_, buf_) do {                                              \
        int k0_ = (c_) << 5;                                                   \
        for (int i = tid; i < 2048; i += 512) {                                \
            int half = i >> 10;                                                \
            int j = i & 1023;                                                  \
            int row = j >> 3, q = j & 7;                                       \
            if (half == 0) {                                                   \
                const float* src = A + (size_t)(m0 + row) * lda + k0_ + q * 4; \
                uint32_t dst = smem_u32 +                                      \
                    ((buf_) * STAGE_F + row * GSTR + q * 4) * 4;               \
                cp_async16(dst, src, 16);                                      \
            } else {                                                           \
                int gr = n0 + row;                                             \
                int ok = (gr < N);                                             \
                const float* src = W + (size_t)(ok ? gr : 0) * ldw + k0_ + q * 4; \
                uint32_t dst = smem_u32 +                                      \
                    ((buf_) * STAGE_F + GBM * GSTR + row * GSTR + q * 4) * 4;  \
                cp_async16(dst, src, ok ? 16 : 0);                             \
            }                                                                  \
        }                                                                      \
    } while (0)

    LOAD_STAGE(0, 0);
    CP_COMMIT();
    if (nch > 1) { LOAD_STAGE(1, 1); }
    CP_COMMIT();

    for (int c = 0; c < nch; c++) {
        CP_WAIT1();
        __syncthreads();
        const int buf = c & 1;
        const float* As = smem + buf * STAGE_F;
        const float* Bs = As + GBM * GSTR;
#pragma unroll
        for (int kk = 0; kk < 32; kk += 8) {
            uint32_t ah[2][4], al[2][4], bh[4][2], bl[4][2];
#pragma unroll
            for (int mt = 0; mt < 2; mt++) {
                const float* ap = As + (warp_m + mt * 16 + gid) * GSTR + kk + tig;
                split_tf(ap[0],            ah[mt][0], al[mt][0]);
                split_tf(ap[8 * GSTR],     ah[mt][1], al[mt][1]);
                split_tf(ap[4],            ah[mt][2], al[mt][2]);
                split_tf(ap[8 * GSTR + 4], ah[mt][3], al[mt][3]);
            }
#pragma unroll
            for (int nt = 0; nt < 4; nt++) {
                const float* bp = Bs + (warp_n + nt * 8 + gid) * GSTR + kk + tig;
                split_tf(bp[0], bh[nt][0], bl[nt][0]);
                split_tf(bp[4], bh[nt][1], bl[nt][1]);
            }
#pragma unroll
            for (int mt = 0; mt < 2; mt++)
#pragma unroll
                for (int nt = 0; nt < 4; nt++) {
                    mma_tf32(acc[mt][nt], al[mt], bh[nt]);
                    mma_tf32(acc[mt][nt], ah[mt], bl[nt]);
                    mma_tf32(acc[mt][nt], ah[mt], bh[nt]);
                }
        }
        __syncthreads();
        if (c + 2 < nch) { LOAD_STAGE(c + 2, buf); }
        CP_COMMIT();
    }

    /* epilogue */
#pragma unroll
    for (int mt = 0; mt < 2; mt++) {
        int r0 = m0 + warp_m + mt * 16 + gid;
#pragma unroll
        for (int nt = 0; nt < 4; nt++) {
            int col = n0 + warp_n + nt * 8 + 2 * tig;
            if (col >= N) continue;
            float v0 = acc[mt][nt][0], v1 = acc[mt][nt][1];
            float v2 = acc[mt][nt][2], v3 = acc[mt][nt][3];
            if (epi == 1) {
                float b0 = bias[col], b1 = bias[col + 1];
                v0 += b0; v1 += b1; v2 += b0; v3 += b1;
                v0 = (v0 > 20.f) ? v0 : log1pf(__expf(v0));
                v1 = (v1 > 20.f) ? v1 : log1pf(__expf(v1));
                v2 = (v2 > 20.f) ? v2 : log1pf(__expf(v2));
                v3 = (v3 > 20.f) ? v3 : log1pf(__expf(v3));
            }
            *(float2*)(C + (size_t)r0 * ldc + col)       = make_float2(v0, v1);
            *(float2*)(C + (size_t)(r0 + 8) * ldc + col) = make_float2(v2, v3);
        }
    }
#undef LOAD_STAGE
}

/* ---------------- depthwise causal conv (D_CONV=4) + bias + silu ---------- */
__global__ __launch_bounds__(256)
void conv_silu_kernel(const float* __restrict__ cw, const float* __restrict__ cb)
{
    int idx = blockIdx.x * 256 + threadIdx.x;
    if (idx >= NROWS * DI) return;
    const int d  = idx & (DI - 1);
    const int bl = idx >> 10;
    const int l  = bl & (SEQ - 1);
    const float* xz = g_scr + OFF_XZ;
    float acc = cb[d];
#pragma unroll
    for (int k = 0; k < 4; k++) {
        int ls = l - 3 + k;
        if (ls >= 0) acc += cw[d * 4 + k] * xz[(size_t)(bl - l + ls) * 2048 + d];
    }
    float sig = 1.f / (1.f + __expf(-acc));
    g_scr[OFF_XC + (size_t)idx] = acc * sig;
}

/* ---------------- selective scan: warp per (b,d), lane = state ------------ */
#define TCH 64
__global__ __launch_bounds__(256)
void scan_kernel(const float* __restrict__ A_log, const float* __restrict__ Dvec)
{
    __shared__ float Bs[TCH][DS];
    __shared__ float Cs[TCH][DS];
    const int warp = threadIdx.x >> 5;
    const int lane = threadIdx.x & 31;
    const int gw = blockIdx.x * 8 + warp;    /* 0..16383 */
    const int b = gw >> 10;
    const int d = gw & (DI - 1);

    const float a  = -__expf(A_log[d * DS + lane]);
    const float Dd = Dvec[d];

    const float* dt_p = g_scr + OFF_DT   + (size_t)(b * SEQ) * DI + d;
    const float* x_p  = g_scr + OFF_XC   + (size_t)(b * SEQ) * DI + d;
    const float* z_p  = g_scr + OFF_XZ   + (size_t)(b * SEQ) * 2048 + DI + d;
    const float* B_p  = g_scr + OFF_XDBC + (size_t)(b * SEQ) * 96 + DTR;
    const float* C_p  = B_p + DS;
    float*       y_p  = g_scr + OFF_Y    + (size_t)(b * SEQ) * DI + d;

    float h = 0.f;
    for (int t0 = 0; t0 < SEQ; t0 += TCH) {
        __syncthreads();
        for (int i = threadIdx.x; i < TCH * DS; i += 256) {
            int tt = i >> 5, s = i & 31;
            Bs[tt][s] = B_p[(size_t)(t0 + tt) * 96 + s];
            Cs[tt][s] = C_p[(size_t)(t0 + tt) * 96 + s];
        }
        __syncthreads();
        for (int tt = 0; tt < TCH; tt++) {
            int t = t0 + tt;
            float dtv = __ldg(dt_p + (size_t)t * DI);
            float xv  = __ldg(x_p  + (size_t)t * DI);
            float zv  = __ldg(z_p  + (size_t)t * 2048);
            float dA = __expf(dtv * a);
            h = fmaf(dA, h, dtv * xv * Bs[tt][lane]);
            float p = h * Cs[tt][lane];
#pragma unroll
            for (int off = 16; off; off >>= 1)
                p += __shfl_xor_sync(0xffffffffu, p, off);
            if (lane == 0) {
                float sig = 1.f / (1.f + __expf(-zv));
                y_p[(size_t)t * DI] = (p + xv * Dd) * zv * sig;
            }
        }
    }
}

/* ---------------- layernorm over D_MODEL=512, writes mout + next-iter u --- */
__global__ __launch_bounds__(512)
void ln_kernel(const float* __restrict__ in, const float* __restrict__ w,
               const float* __restrict__ bb, int iter)
{
    const int row = blockIdx.x;   /* 0..8191 = b*512+t */
    const int d = threadIdx.x;
    float v = in[(size_t)row * DM + d];
    float s = v, s2 = v * v;
#pragma unroll
    for (int off = 16; off; off >>= 1) {
        s  += __shfl_xor_sync(0xffffffffu, s,  off);
        s2 += __shfl_xor_sync(0xffffffffu, s2, off);
    }
    __shared__ float sh1[16], sh2[16];
    __shared__ float mu_s, rs_s;
    const int wid = d >> 5, lane = d & 31;
    if (lane == 0) { sh1[wid] = s; sh2[wid] = s2; }
    __syncthreads();
    if (d < 32) {
        float aa = (d < 16) ? sh1[d] : 0.f;
        float cc = (d < 16) ? sh2[d] : 0.f;
#pragma unroll
        for (int off = 8; off; off >>= 1) {
            aa += __shfl_xor_sync(0xffffffffu, aa, off);
            cc += __shfl_xor_sync(0xffffffffu, cc, off);
        }
        if (d == 0) {
            float mu = aa / (float)DM;
            float var = cc / (float)DM - mu * mu;
            mu_s = mu;
            rs_s = rsqrtf(var + 1e-5f);
        }
    }
    __syncthreads();
    float o = (v - mu_s) * rs_s * w[d] + bb[d];
    const int bidx = row >> 9, t = row & 511;
    g_scr[OFF_MOUT + (((size_t)bidx * 1024) + (size_t)iter * SEQ + t) * DM + d] = o;
    g_scr[OFF_U + (size_t)row * DM + d] = o;
}

/* ---------------- launch --------------------------------------------------- */
extern "C" void kernel_launch(void* const* d_in, const int* in_sizes, int n_in,
                              void* d_out, int out_size)
{
    const float* x_enc      = (const float*)d_in[0];
    const float* x_mark_enc = (const float*)d_in[1];
    const float* conv_emb_w = (const float*)d_in[4];
    const float* temp_w     = (const float*)d_in[5];
    const float* in_proj_w  = (const float*)d_in[6];
    const float* conv1d_w   = (const float*)d_in[7];
    const float* conv1d_b   = (const float*)d_in[8];
    const float* x_proj_w   = (const float*)d_in[9];
    const float* dt_proj_w  = (const float*)d_in[10];
    const float* dt_proj_b  = (const float*)d_in[11];
    const float* A_log      = (const float*)d_in[12];
    const float* Dvec       = (const float*)d_in[13];
    const float* out_proj_w = (const float*)d_in[14];
    const float* ln_w       = (const float*)d_in[15];
    const float* ln_b       = (const float*)d_in[16];
    const float* head_w     = (const float*)d_in[17];
    float* out = (float*)d_out;

    cudaFuncSetAttribute(gemm_mma, cudaFuncAttributeMaxDynamicSharedMemorySize,
                         GT_SMEM_BYTES);

    float* scr = nullptr;
    cudaGetSymbolAddress((void**)&scr, g_scr);
    float* u    = scr + OFF_U;
    float* xz   = scr + OFF_XZ;
    float* xc   = scr + OFF_XC;
    float* xdbc = scr + OFF_XDBC;
    float* dt   = scr + OFF_DT;
    float* y    = scr + OFF_Y;
    float* lnin = scr + OFF_LNIN;
    float* mout = scr + OFF_MOUT;

    emb_kernel<<<256, 512>>>(x_enc, x_mark_enc, conv_emb_w, temp_w);

    for (int iter = 0; iter < 2; iter++) {
        /* xz = u @ in_proj^T : (8192,2048), K=512 */
        gemm_mma<<<dim3(2048 / GBN, 8192 / GBM), 512, GT_SMEM_BYTES>>>(
            u, in_proj_w, xz, nullptr, 8192, 2048, 512, 512, 512, 2048, 0);
        /* depthwise conv + silu -> xc */
        conv_silu_kernel<<<(NROWS * DI) / 256, 256>>>(conv1d_w, conv1d_b);
        /* xdbc = xc @ x_proj^T : (8192,96), K=1024 */
        gemm_mma<<<dim3(1, 8192 / GBM), 512, GT_SMEM_BYTES>>>(
            xc, x_proj_w, xdbc, nullptr, 8192, 96, 1024, 1024, 1024, 96, 0);
        /* dt = softplus(xdbc[:,:32] @ dt_proj^T + b) : (8192,1024), K=32 */
        gemm_mma<<<dim3(1024 / GBN, 8192 / GBM), 512, GT_SMEM_BYTES>>>(
            xdbc, dt_proj_w, dt, dt_proj_b, 8192, 1024, 32, 96, 32, 1024, 1);
        /* selective scan + gating -> y */
        scan_kernel<<<2048, 256>>>(A_log, Dvec);
        /* lnin = y @ out_proj^T : (8192,512), K=1024 */
        gemm_mma<<<dim3(512 / GBN, 8192 / GBM), 512, GT_SMEM_BYTES>>>(
            y, out_proj_w, lnin, nullptr, 8192, 512, 1024, 1024, 1024, 512, 0);
        /* layernorm -> mout slice + next u */
        ln_kernel<<<8192, 512>>>(lnin, ln_w, ln_b, iter);
    }

    /* out = mout @ head^T : (16384,32), K=512 */
    gemm_mma<<<dim3(1, 16384 / GBM), 512, GT_SMEM_BYTES>>>(
        mout, head_w, out, nullptr, 16384, 32, 512, 512, 512, 32, 0);
}

// round 7
// speedup vs baseline: 1.2816x; 1.1174x over previous
#include <cuda_runtime.h>
#include <math.h>
#include <cstdint>

#define BSZ 16
#define SEQ 512
#define DM 512
#define DI 1024
#define DS 32
#define DTR 32
#define NROWS (BSZ*SEQ)   /* 8192 */

/* ---------------- scratch (static device memory; no allocations) ---------- */
#define OFF_U    ((size_t)0)
#define OFF_XZ   (OFF_U    + (size_t)NROWS*DM)
#define OFF_XC   (OFF_XZ   + (size_t)NROWS*2*DI)
#define OFF_XDBC (OFF_XC   + (size_t)NROWS*DI)
#define OFF_DT   (OFF_XDBC + (size_t)NROWS*96)
#define OFF_Y    (OFF_DT   + (size_t)NROWS*DI)
#define OFF_LNIN (OFF_Y    + (size_t)NROWS*DI)
#define OFF_MOUT (OFF_LNIN + (size_t)NROWS*DM)
#define SCR_TOTAL (OFF_MOUT + (size_t)2*NROWS*DM)

__device__ __align__(16) float g_scr[SCR_TOTAL];

/* ---------------- embedding: conv token embed + temporal + positional ----- */
__global__ __launch_bounds__(512)
void emb_kernel(const float* __restrict__ x_enc, const float* __restrict__ x_mark,
                const float* __restrict__ cw, const float* __restrict__ tw)
{
    __shared__ float xs[34][32];
    __shared__ float xm[32][4];
    const int b  = blockIdx.x >> 4;
    const int l0 = (blockIdx.x & 15) * 32;
    const int d  = threadIdx.x;

    for (int i = d; i < 34 * 32; i += 512) {
        int r = i >> 5, c = i & 31;
        int g = l0 - 2 + r;
        g = max(0, min(SEQ - 1, g));
        xs[r][c] = x_enc[((size_t)b * SEQ + g) * 32 + c];
    }
    for (int i = d; i < 32 * 4; i += 512) {
        int r = i >> 2, m = i & 3;
        xm[r][m] = x_mark[((size_t)b * SEQ + l0 + r) * 4 + m];
    }
    __syncthreads();

    float w[96];
#pragma unroll
    for (int i = 0; i < 96; i++) w[i] = cw[d * 96 + i];
    const float t0w = tw[d * 4 + 0], t1w = tw[d * 4 + 1];
    const float t2w = tw[d * 4 + 2], t3w = tw[d * 4 + 3];
    const float divv = __expf(-(float)(d & ~1) * (9.2103403719761836f / 512.f));

    for (int ll = 0; ll < 32; ll++) {
        int l = l0 + ll;
        float ang = (float)l * divv;
        float acc = (d & 1) ? cosf(ang) : sinf(ang);
        acc += t0w * xm[ll][0] + t1w * xm[ll][1] + t2w * xm[ll][2] + t3w * xm[ll][3];
#pragma unroll
        for (int ci = 0; ci < 32; ci++) {
            acc += w[ci * 3 + 0] * xs[ll + 0][ci];
            acc += w[ci * 3 + 1] * xs[ll + 1][ci];
            acc += w[ci * 3 + 2] * xs[ll + 2][ci];
        }
        g_scr[OFF_U + ((size_t)b * SEQ + l) * DM + d] = acc;
    }
}

/* ====== bf16 3-term split tensor GEMM: C[M,N] = A[M,K] * W[N,K]^T ========= */
/* a = ah + al (bf16 each); acc += ah*bh + ah*bl + al*bh  (near-fp32).
   mma.sync.m16n8k16.bf16. Block 128x64, 8 warps (4x2), warp 32x32.
   hi/lo split done ONCE per element at load; smem holds packed bf16x2 words.
   K consumed in chunks of 32. epi==1: softplus(v + bias[n]).                */
#define GBM 128
#define GBN 64
#define ASTR 20                            /* padded words per row */
#define A_LO_OFF (128*ASTR)
#define B_HI_OFF (2*128*ASTR)
#define B_LO_OFF (2*128*ASTR + 64*ASTR)
#define STAGE_W  (2*128*ASTR + 2*64*ASTR)  /* 7680 words / stage */
#define GT_SMEM_BYTES (2*STAGE_W*4)        /* 61440 B */

__device__ __forceinline__ void split_pair(float v0, float v1,
                                           uint32_t& hw, uint32_t& lw) {
    asm("cvt.rn.bf16x2.f32 %0, %1, %2;" : "=r"(hw) : "f"(v1), "f"(v0));
    float h0 = __uint_as_float(hw << 16);
    float h1 = __uint_as_float(hw & 0xffff0000u);
    asm("cvt.rn.bf16x2.f32 %0, %1, %2;" : "=r"(lw) : "f"(v1 - h1), "f"(v0 - h0));
}

__device__ __forceinline__ void mma_bf16(float* c, const uint32_t* a, const uint32_t* b) {
    asm volatile(
        "mma.sync.aligned.m16n8k16.row.col.f32.bf16.bf16.f32 "
        "{%0,%1,%2,%3}, {%4,%5,%6,%7}, {%8,%9}, {%0,%1,%2,%3};"
        : "+f"(c[0]), "+f"(c[1]), "+f"(c[2]), "+f"(c[3])
        : "r"(a[0]), "r"(a[1]), "r"(a[2]), "r"(a[3]), "r"(b[0]), "r"(b[1]));
}

__global__ __launch_bounds__(256, 2)
void gemm_mma(const float* __restrict__ A, const float* __restrict__ W,
              float* __restrict__ C, const float* __restrict__ bias,
              int M, int N, int K, int lda, int ldw, int ldc, int epi)
{
    extern __shared__ __align__(16) uint32_t smem[];
    const int tid = threadIdx.x;
    const int wid = tid >> 5;
    const int lane = tid & 31;
    const int m0 = blockIdx.y * GBM;
    const int n0 = blockIdx.x * GBN;
    const int warp_m = (wid >> 1) * 32;   /* 0,32,64,96 */
    const int warp_n = (wid & 1) * 32;    /* 0,32 */
    const int gid = lane >> 2;
    const int tig = lane & 3;

    float acc[2][4][4];
#pragma unroll
    for (int i = 0; i < 2; i++)
#pragma unroll
        for (int j = 0; j < 4; j++)
#pragma unroll
            for (int k = 0; k < 4; k++) acc[i][j][k] = 0.f;

    /* loader assignment */
    const int arow = tid >> 1, ahalf = tid & 1;          /* A: half row each */
    const int brow = tid >> 2, bq = tid & 3;             /* B: quarter row   */
    const float* Aptr = A + (size_t)(m0 + arow) * lda + ahalf * 16;
    const int wr = n0 + brow;
    const bool wok = wr < N;
    const float* Wptr = W + (size_t)(wok ? wr : 0) * ldw + bq * 8;

    float4 ar[4], br[2];
    const int nch = K >> 5;

#define LOADG(k0_) do {                                                        \
        ar[0] = *(const float4*)(Aptr + (k0_));                                \
        ar[1] = *(const float4*)(Aptr + (k0_) + 4);                            \
        ar[2] = *(const float4*)(Aptr + (k0_) + 8);                            \
        ar[3] = *(const float4*)(Aptr + (k0_) + 12);                           \
        if (wok) {                                                             \
            br[0] = *(const float4*)(Wptr + (k0_));                            \
            br[1] = *(const float4*)(Wptr + (k0_) + 4);                        \
        } else {                                                               \
            br[0] = make_float4(0, 0, 0, 0);                                   \
            br[1] = make_float4(0, 0, 0, 0);                                   \
        }                                                                      \
    } while (0)

    LOADG(0);

    for (int c = 0; c < nch; c++) {
        const int buf = c & 1;
        /* convert + store stage */
        {
            uint32_t* s  = smem + buf * STAGE_W;
            uint32_t* ah = s + arow * ASTR + ahalf * 8;
            uint32_t* al = ah + A_LO_OFF;
#pragma unroll
            for (int i = 0; i < 4; i++) {
                uint32_t h0, l0, h1, l1;
                split_pair(ar[i].x, ar[i].y, h0, l0);
                split_pair(ar[i].z, ar[i].w, h1, l1);
                ah[i * 2] = h0; ah[i * 2 + 1] = h1;
                al[i * 2] = l0; al[i * 2 + 1] = l1;
            }
            uint32_t* bh = s + B_HI_OFF + brow * ASTR + bq * 4;
            uint32_t* bl = bh + (B_LO_OFF - B_HI_OFF);
#pragma unroll
            for (int i = 0; i < 2; i++) {
                uint32_t h0, l0, h1, l1;
                split_pair(br[i].x, br[i].y, h0, l0);
                split_pair(br[i].z, br[i].w, h1, l1);
                bh[i * 2] = h0; bh[i * 2 + 1] = h1;
                bl[i * 2] = l0; bl[i * 2 + 1] = l1;
            }
        }
        if (c + 1 < nch) { LOADG((c + 1) << 5); }
        __syncthreads();
        /* compute on buf */
        {
            const uint32_t* s = smem + buf * STAGE_W;
#pragma unroll
            for (int ks = 0; ks < 2; ks++) {
                uint32_t ah[2][4], al[2][4], bh[2][2], bl[2][2];
#pragma unroll
                for (int mt = 0; mt < 2; mt++) {
                    const uint32_t* p = s + (warp_m + mt * 16 + gid) * ASTR + ks * 8 + tig;
                    ah[mt][0] = p[0];
                    ah[mt][1] = p[8 * ASTR];
                    ah[mt][2] = p[4];
                    ah[mt][3] = p[8 * ASTR + 4];
                    const uint32_t* q = p + A_LO_OFF;
                    al[mt][0] = q[0];
                    al[mt][1] = q[8 * ASTR];
                    al[mt][2] = q[4];
                    al[mt][3] = q[8 * ASTR + 4];
                }
                /* process 4 n-tiles in 2 groups to limit regs */
#pragma unroll
                for (int ng = 0; ng < 2; ng++) {
#pragma unroll
                    for (int nn = 0; nn < 2; nn++) {
                        int nt = ng * 2 + nn;
                        const uint32_t* p = s + B_HI_OFF +
                            (warp_n + nt * 8 + gid) * ASTR + ks * 8 + tig;
                        bh[nn][0] = p[0];
                        bh[nn][1] = p[4];
                        const uint32_t* q = p + (B_LO_OFF - B_HI_OFF);
                        bl[nn][0] = q[0];
                        bl[nn][1] = q[4];
                    }
#pragma unroll
                    for (int mt = 0; mt < 2; mt++)
#pragma unroll
                        for (int nn = 0; nn < 2; nn++) {
                            int nt = ng * 2 + nn;
                            mma_bf16(acc[mt][nt], ah[mt], bl[nn]);
                            mma_bf16(acc[mt][nt], al[mt], bh[nn]);
                            mma_bf16(acc[mt][nt], ah[mt], bh[nn]);
                        }
                }
            }
        }
        __syncthreads();
    }
#undef LOADG

    /* epilogue */
#pragma unroll
    for (int mt = 0; mt < 2; mt++) {
        int r0 = m0 + warp_m + mt * 16 + gid;
#pragma unroll
        for (int nt = 0; nt < 4; nt++) {
            int col = n0 + warp_n + nt * 8 + 2 * tig;
            if (col >= N) continue;
            float v0 = acc[mt][nt][0], v1 = acc[mt][nt][1];
            float v2 = acc[mt][nt][2], v3 = acc[mt][nt][3];
            if (epi == 1) {
                float b0 = bias[col], b1 = bias[col + 1];
                v0 += b0; v1 += b1; v2 += b0; v3 += b1;
                v0 = (v0 > 20.f) ? v0 : log1pf(__expf(v0));
                v1 = (v1 > 20.f) ? v1 : log1pf(__expf(v1));
                v2 = (v2 > 20.f) ? v2 : log1pf(__expf(v2));
                v3 = (v3 > 20.f) ? v3 : log1pf(__expf(v3));
            }
            *(float2*)(C + (size_t)r0 * ldc + col)       = make_float2(v0, v1);
            *(float2*)(C + (size_t)(r0 + 8) * ldc + col) = make_float2(v2, v3);
        }
    }
}

/* ---------------- depthwise causal conv (D_CONV=4) + bias + silu ---------- */
__global__ __launch_bounds__(256)
void conv_silu_kernel(const float* __restrict__ cw, const float* __restrict__ cb)
{
    int idx = blockIdx.x * 256 + threadIdx.x;
    if (idx >= NROWS * DI) return;
    const int d  = idx & (DI - 1);
    const int bl = idx >> 10;
    const int l  = bl & (SEQ - 1);
    const float* xz = g_scr + OFF_XZ;
    float acc = cb[d];
#pragma unroll
    for (int k = 0; k < 4; k++) {
        int ls = l - 3 + k;
        if (ls >= 0) acc += cw[d * 4 + k] * xz[(size_t)(bl - l + ls) * 2048 + d];
    }
    float sig = 1.f / (1.f + __expf(-acc));
    g_scr[OFF_XC + (size_t)idx] = acc * sig;
}

/* ---------------- selective scan: warp per (b,d), lane = state ------------ */
#define TCH 64
__global__ __launch_bounds__(256)
void scan_kernel(const float* __restrict__ A_log, const float* __restrict__ Dvec)
{
    __shared__ float Bs[TCH][DS];
    __shared__ float Cs[TCH][DS];
    const int warp = threadIdx.x >> 5;
    const int lane = threadIdx.x & 31;
    const int gw = blockIdx.x * 8 + warp;    /* 0..16383 */
    const int b = gw >> 10;
    const int d = gw & (DI - 1);

    const float a  = -__expf(A_log[d * DS + lane]);
    const float Dd = Dvec[d];

    const float* dt_p = g_scr + OFF_DT   + (size_t)(b * SEQ) * DI + d;
    const float* x_p  = g_scr + OFF_XC   + (size_t)(b * SEQ) * DI + d;
    const float* z_p  = g_scr + OFF_XZ   + (size_t)(b * SEQ) * 2048 + DI + d;
    const float* B_p  = g_scr + OFF_XDBC + (size_t)(b * SEQ) * 96 + DTR;
    const float* C_p  = B_p + DS;
    float*       y_p  = g_scr + OFF_Y    + (size_t)(b * SEQ) * DI + d;

    float h = 0.f;
    for (int t0 = 0; t0 < SEQ; t0 += TCH) {
        __syncthreads();
        for (int i = threadIdx.x; i < TCH * DS; i += 256) {
            int tt = i >> 5, s = i & 31;
            Bs[tt][s] = B_p[(size_t)(t0 + tt) * 96 + s];
            Cs[tt][s] = C_p[(size_t)(t0 + tt) * 96 + s];
        }
        __syncthreads();
        for (int tt = 0; tt < TCH; tt++) {
            int t = t0 + tt;
            float dtv = __ldg(dt_p + (size_t)t * DI);
            float xv  = __ldg(x_p  + (size_t)t * DI);
            float zv  = __ldg(z_p  + (size_t)t * 2048);
            float dA = __expf(dtv * a);
            h = fmaf(dA, h, dtv * xv * Bs[tt][lane]);
            float p = h * Cs[tt][lane];
#pragma unroll
            for (int off = 16; off; off >>= 1)
                p += __shfl_xor_sync(0xffffffffu, p, off);
            if (lane == 0) {
                float sig = 1.f / (1.f + __expf(-zv));
                y_p[(size_t)t * DI] = (p + xv * Dd) * zv * sig;
            }
        }
    }
}

/* ---------------- layernorm over D_MODEL=512, writes mout + next-iter u --- */
__global__ __launch_bounds__(512)
void ln_kernel(const float* __restrict__ in, const float* __restrict__ w,
               const float* __restrict__ bb, int iter)
{
    const int row = blockIdx.x;   /* 0..8191 = b*512+t */
    const int d = threadIdx.x;
    float v = in[(size_t)row * DM + d];
    float s = v, s2 = v * v;
#pragma unroll
    for (int off = 16; off; off >>= 1) {
        s  += __shfl_xor_sync(0xffffffffu, s,  off);
        s2 += __shfl_xor_sync(0xffffffffu, s2, off);
    }
    __shared__ float sh1[16], sh2[16];
    __shared__ float mu_s, rs_s;
    const int wid = d >> 5, lane = d & 31;
    if (lane == 0) { sh1[wid] = s; sh2[wid] = s2; }
    __syncthreads();
    if (d < 32) {
        float aa = (d < 16) ? sh1[d] : 0.f;
        float cc = (d < 16) ? sh2[d] : 0.f;
#pragma unroll
        for (int off = 8; off; off >>= 1) {
            aa += __shfl_xor_sync(0xffffffffu, aa, off);
            cc += __shfl_xor_sync(0xffffffffu, cc, off);
        }
        if (d == 0) {
            float mu = aa / (float)DM;
            float var = cc / (float)DM - mu * mu;
            mu_s = mu;
            rs_s = rsqrtf(var + 1e-5f);
        }
    }
    __syncthreads();
    float o = (v - mu_s) * rs_s * w[d] + bb[d];
    const int bidx = row >> 9, t = row & 511;
    g_scr[OFF_MOUT + (((size_t)bidx * 1024) + (size_t)iter * SEQ + t) * DM + d] = o;
    g_scr[OFF_U + (size_t)row * DM + d] = o;
}

/* ---------------- launch --------------------------------------------------- */
extern "C" void kernel_launch(void* const* d_in, const int* in_sizes, int n_in,
                              void* d_out, int out_size)
{
    const float* x_enc      = (const float*)d_in[0];
    const float* x_mark_enc = (const float*)d_in[1];
    const float* conv_emb_w = (const float*)d_in[4];
    const float* temp_w     = (const float*)d_in[5];
    const float* in_proj_w  = (const float*)d_in[6];
    const float* conv1d_w   = (const float*)d_in[7];
    const float* conv1d_b   = (const float*)d_in[8];
    const float* x_proj_w   = (const float*)d_in[9];
    const float* dt_proj_w  = (const float*)d_in[10];
    const float* dt_proj_b  = (const float*)d_in[11];
    const float* A_log      = (const float*)d_in[12];
    const float* Dvec       = (const float*)d_in[13];
    const float* out_proj_w = (const float*)d_in[14];
    const float* ln_w       = (const float*)d_in[15];
    const float* ln_b       = (const float*)d_in[16];
    const float* head_w     = (const float*)d_in[17];
    float* out = (float*)d_out;

    cudaFuncSetAttribute(gemm_mma, cudaFuncAttributeMaxDynamicSharedMemorySize,
                         GT_SMEM_BYTES);

    float* scr = nullptr;
    cudaGetSymbolAddress((void**)&scr, g_scr);
    float* u    = scr + OFF_U;
    float* xz   = scr + OFF_XZ;
    float* xc   = scr + OFF_XC;
    float* xdbc = scr + OFF_XDBC;
    float* dt   = scr + OFF_DT;
    float* y    = scr + OFF_Y;
    float* lnin = scr + OFF_LNIN;
    float* mout = scr + OFF_MOUT;

    emb_kernel<<<256, 512>>>(x_enc, x_mark_enc, conv_emb_w, temp_w);

    for (int iter = 0; iter < 2; iter++) {
        /* xz = u @ in_proj^T : (8192,2048), K=512 */
        gemm_mma<<<dim3(2048 / GBN, 8192 / GBM), 256, GT_SMEM_BYTES>>>(
            u, in_proj_w, xz, nullptr, 8192, 2048, 512, 512, 512, 2048, 0);
        /* depthwise conv + silu -> xc */
        conv_silu_kernel<<<(NROWS * DI) / 256, 256>>>(conv1d_w, conv1d_b);
        /* xdbc = xc @ x_proj^T : (8192,96), K=1024 */
        gemm_mma<<<dim3(2, 8192 / GBM), 256, GT_SMEM_BYTES>>>(
            xc, x_proj_w, xdbc, nullptr, 8192, 96, 1024, 1024, 1024, 96, 0);
        /* dt = softplus(xdbc[:,:32] @ dt_proj^T + b) : (8192,1024), K=32 */
        gemm_mma<<<dim3(1024 / GBN, 8192 / GBM), 256, GT_SMEM_BYTES>>>(
            xdbc, dt_proj_w, dt, dt_proj_b, 8192, 1024, 32, 96, 32, 1024, 1);
        /* selective scan + gating -> y */
        scan_kernel<<<2048, 256>>>(A_log, Dvec);
        /* lnin = y @ out_proj^T : (8192,512), K=1024 */
        gemm_mma<<<dim3(512 / GBN, 8192 / GBM), 256, GT_SMEM_BYTES>>>(
            y, out_proj_w, lnin, nullptr, 8192, 512, 1024, 1024, 1024, 512, 0);
        /* layernorm -> mout slice + next u */
        ln_kernel<<<8192, 512>>>(lnin, ln_w, ln_b, iter);
    }

    /* out = mout @ head^T : (16384,32), K=512 */
    gemm_mma<<<dim3(1, 16384 / GBM), 256, GT_SMEM_BYTES>>>(
        mout, head_w, out, nullptr, 16384, 32, 512, 512, 512, 32, 0);
}